// round 3
// baseline (speedup 1.0000x reference)
#include <cuda_runtime.h>
#include <cstdint>

// Problem constants
#define BB 8
#define TT 128
#define DD 1024
#define VV 4096
#define RR 16
#define HH 2
#define GG (VV * RR * HH)  // 131072 rows of W

typedef unsigned long long ull;

// Scratch (device globals — no allocation allowed)
__device__ float g_S[256];  // [b][h][r] sums of exp
__device__ float g_E[256];  // [b][h][r] selected-row exps

__device__ __forceinline__ void fma2(ull& d, ull a, ull b) {
    asm("fma.rn.f32x2 %0, %1, %2, %0;" : "+l"(d) : "l"(a), "l"(b));
}
__device__ __forceinline__ ull packw(float f) {
    ull r;
    asm("mov.b64 %0, {%1, %1};" : "=l"(r) : "r"(__float_as_uint(f)));
    return r;
}
__device__ __forceinline__ float lo32(ull a) { return __uint_as_float((unsigned)a); }
__device__ __forceinline__ float hi32(ull a) { return __uint_as_float((unsigned)(a >> 32)); }

__global__ void k_zero() {
    g_S[threadIdx.x] = 0.f;
    g_E[threadIdx.x] = 0.f;
}

// Per-row epilogue: bias + exp, accumulate S (smem), capture selected rows into g_E.
// s must be a register array with constant indices after inlining (no q-select pointer!).
__device__ __forceinline__ void emit_row(int g, const float s[8], float* sblk,
                                         const int* spts, const float* __restrict__ bias) {
    float bi = __ldg(&bias[g]);
    int hidx = g >> 16;            // g = h*65536 + v*16 + r
    int v    = (g >> 4) & (VV - 1);
    int rr   = g & (RR - 1);
    int base = hidx * 16 + rr;
#pragma unroll
    for (int b = 0; b < 8; b++) {
        float ev = expf(s[b] + bi);
        atomicAdd(&sblk[b * 32 + base], ev);
        if (v == spts[b * 2 + hidx]) g_E[b * 32 + base] = ev;
    }
}

// Main pass: block = 256 threads (8 warps), each warp owns 8 rows of W.
// Lane layout: rgrp = lane>>3 picks row within quad, c = lane&7 picks the 16B column slice.
// W loads are fully coalesced LDG.128 (4 rows x 128B contiguous per request).
// h lives in smem, XOR-swizzled so the 8 c-groups hit distinct bank groups (1 wf / LDS.128).
__global__ void __launch_bounds__(256, 2) k_main(const float* __restrict__ lhs,
                                                 const float* __restrict__ Wm,
                                                 const float* __restrict__ bias,
                                                 const void* __restrict__ pts_raw) {
    __shared__ float hs[8192];   // swizzled h_last: 8 batches x 1024, batch-major per k in float4 halves
    __shared__ float sblk[256];  // block-local S accumulation
    __shared__ int spts[16];     // points, width-detected

    const int tid = threadIdx.x;

    if (tid < 16) {
        // Detect int64 vs int32 points: values < 4096, so int64 data has all-zero hi words.
        // Read exactly 64B (safe for both widths).
        const ull* pw = (const ull*)pts_raw;
        ull h = 0;
#pragma unroll
        for (int i = 0; i < 8; i++) h |= (pw[i] >> 32);
        bool is64 = (h == 0ULL);
        spts[tid] = is64 ? (int)((const long long*)pts_raw)[tid]
                         : ((const int*)pts_raw)[tid];
    }
    sblk[tid] = 0.f;

    // Stage h_last[b][k] = lhs[b, T-1, k] with XOR swizzle on 16B chunks.
#pragma unroll
    for (int i = 0; i < 32; i++) {
        int idx = tid + i * 256;
        int b = idx >> 10, k = idx & 1023;
        int idx16 = k * 2 + (b >> 2);
        int s = idx16 ^ ((idx16 >> 3) & 7);
        hs[s * 4 + (b & 3)] = lhs[b * (TT * DD) + (TT - 1) * DD + k];
    }
    __syncthreads();

    const int warp = tid >> 5, lane = tid & 31;
    const int rgrp = lane >> 3, c = lane & 7;
    const int rowbase = blockIdx.x * 64 + warp * 8;
    const int row0 = rowbase + rgrp;       // quad 0
    const int row1 = rowbase + 4 + rgrp;   // quad 1

    const float4* p0 = (const float4*)Wm + (size_t)row0 * 256 + c;
    const float4* p1 = (const float4*)Wm + (size_t)row1 * 256 + c;
    const ulonglong2* h8 = (const ulonglong2*)hs;

    // 8 packed-f32x2 accumulators per row: pair p holds batches (2p, 2p+1)
    ull a0[4] = {0, 0, 0, 0};
    ull a1[4] = {0, 0, 0, 0};

    float4 w0 = p0[0];
    float4 w1 = p1[0];

#pragma unroll 2
    for (int j = 0; j < 32; j++) {
        int jn = (j + 1) & 31;  // wrap: last iter reloads j=0 (L1 hit, harmless, branchless)
        float4 n0 = p0[jn * 8];
        float4 n1 = p1[jn * 8];
        int k0 = j * 32 + c * 4;
#define STEP(wa, wb, kk)                                          \
    do {                                                          \
        int idx16 = (k0 + (kk)) * 2;                              \
        int sw = (idx16 >> 3) & 7;                                \
        ulonglong2 hA = h8[idx16 ^ sw];       /* batches 0-3 */   \
        ulonglong2 hB = h8[(idx16 + 1) ^ sw]; /* batches 4-7 */   \
        ull wd0 = packw(wa);                                      \
        fma2(a0[0], wd0, hA.x); fma2(a0[1], wd0, hA.y);           \
        fma2(a0[2], wd0, hB.x); fma2(a0[3], wd0, hB.y);           \
        ull wd1 = packw(wb);                                      \
        fma2(a1[0], wd1, hA.x); fma2(a1[1], wd1, hA.y);           \
        fma2(a1[2], wd1, hB.x); fma2(a1[3], wd1, hB.y);           \
    } while (0)
        STEP(w0.x, w1.x, 0);
        STEP(w0.y, w1.y, 1);
        STEP(w0.z, w1.z, 2);
        STEP(w0.w, w1.w, 3);
#undef STEP
        w0 = n0;
        w1 = n1;
    }

    // Unpack to scalar partials, butterfly-reduce across the 8 lanes sharing each row
    // (xor masks 4,2,1 stay within the c-group; rgrp preserved).
    float s0[8], s1[8];
#pragma unroll
    for (int p = 0; p < 4; p++) {
        s0[2 * p] = lo32(a0[p]); s0[2 * p + 1] = hi32(a0[p]);
        s1[2 * p] = lo32(a1[p]); s1[2 * p + 1] = hi32(a1[p]);
    }
#pragma unroll
    for (int m = 4; m >= 1; m >>= 1) {
#pragma unroll
        for (int b = 0; b < 8; b++) {
            s0[b] += __shfl_xor_sync(0xffffffffu, s0[b], m);
            s1[b] += __shfl_xor_sync(0xffffffffu, s1[b], m);
        }
    }

    if (c == 0) {
        emit_row(row0, s0, sblk, spts, bias);
        emit_row(row1, s1, sblk, spts, bias);
    }
    __syncthreads();
    atomicAdd(&g_S[tid], sblk[tid]);  // one global atomic per slot per block
}

// Final contraction: out[0:8] = p_eval, out[8:16] = norm_const
__global__ void k_final(float* __restrict__ out) {
    int b = threadIdx.x;
    if (b < 8) {
        float n = 0.f, p = 0.f;
#pragma unroll
        for (int rr = 0; rr < 16; rr++) {
            n += g_S[b * 32 + rr] * g_S[b * 32 + 16 + rr];
            p += g_E[b * 32 + rr] * g_E[b * 32 + 16 + rr];
        }
        out[b] = p;
        out[8 + b] = n;
    }
}

extern "C" void kernel_launch(void* const* d_in, const int* in_sizes, int n_in,
                              void* d_out, int out_size) {
    // Identify inputs by element count (robust to ordering)
    const float* lhs = nullptr;
    const float* Wm = nullptr;
    const float* bias = nullptr;
    const void* pts = nullptr;
    for (int i = 0; i < n_in; i++) {
        int sz = in_sizes[i];
        if (sz == GG * DD / 1 && sz == 134217728) Wm = (const float*)d_in[i];
        else if (sz == BB * TT * DD) lhs = (const float*)d_in[i];
        else if (sz == GG) bias = (const float*)d_in[i];
        else if (sz == BB * HH) pts = d_in[i];
    }
    // Fallback to declared order if sizes don't match expectations
    if (!lhs) lhs = (const float*)d_in[0];
    if (!Wm) Wm = (const float*)d_in[1];
    if (!bias) bias = (const float*)d_in[2];
    if (!pts) pts = d_in[3];

    k_zero<<<1, 256>>>();
    k_main<<<GG / 64, 256>>>(lhs, Wm, bias, pts);
    k_final<<<1, 32>>>((float*)d_out);
}

// round 4
// speedup vs baseline: 1.0694x; 1.0694x over previous
#include <cuda_runtime.h>
#include <cstdint>

// Problem constants
#define BB 8
#define TT 128
#define DD 1024
#define VV 4096
#define RR 16
#define HH 2
#define GG (VV * RR * HH)  // 131072 rows of W
#define NBLK 1024          // 128 rows per block

typedef unsigned long long ull;

// Scratch (device globals — no allocation allowed)
__device__ float g_Spart[NBLK][128];  // per-block partial S: [block][r*8 + b]
__device__ float g_E[256];            // [b][h][r] selected-row exps (written exactly once each)
__device__ unsigned g_count = 0;      // last-block-done counter (reset by last block)

__device__ __forceinline__ void fma2(ull& d, ull a, ull b) {
    asm("fma.rn.f32x2 %0, %1, %2, %0;" : "+l"(d) : "l"(a), "l"(b));
}
__device__ __forceinline__ ull packw(float f) {
    ull r;
    asm("mov.b64 %0, {%1, %1};" : "=l"(r) : "r"(__float_as_uint(f)));
    return r;
}
__device__ __forceinline__ float lo32(ull a) { return __uint_as_float((unsigned)a); }
__device__ __forceinline__ float hi32(ull a) { return __uint_as_float((unsigned)(a >> 32)); }

// Reduce-scatter across the 8-lane c-group: on entry s[b] = lane-partial for batch b;
// on exit lane c holds the full (8-lane) sum for batch c. 7 shuffles.
__device__ __forceinline__ float rscatter8(const float s[8], int c) {
    bool b4 = (c & 4) != 0;
    float kp[4], snd[4];
#pragma unroll
    for (int i = 0; i < 4; i++) { snd[i] = b4 ? s[i] : s[i + 4]; kp[i] = b4 ? s[i + 4] : s[i]; }
#pragma unroll
    for (int i = 0; i < 4; i++) kp[i] += __shfl_xor_sync(0xffffffffu, snd[i], 4);
    bool b2 = (c & 2) != 0;
    float k2[2], s2[2];
#pragma unroll
    for (int i = 0; i < 2; i++) { s2[i] = b2 ? kp[i] : kp[i + 2]; k2[i] = b2 ? kp[i + 2] : kp[i]; }
#pragma unroll
    for (int i = 0; i < 2; i++) k2[i] += __shfl_xor_sync(0xffffffffu, s2[i], 2);
    bool b1 = (c & 1) != 0;
    float s1 = b1 ? k2[0] : k2[1];
    float k1 = b1 ? k2[1] : k2[0];
    return k1 + __shfl_xor_sync(0xffffffffu, s1, 1);
}

// Single fused kernel. Block = 256 threads (8 warps). Each warp owns 16 rows of W
// as 4 independent load streams (quads), giving 4 outstanding LDG.128 per thread.
// Lane layout: rgrp = lane>>3 picks row within a quad, c = lane&7 picks the 16B
// column slice. W loads are coalesced LDG.128 (streaming). h lives in smem,
// XOR-swizzled so the 8 c-groups hit distinct bank groups.
__global__ void __launch_bounds__(256, 2) k_main(const float* __restrict__ lhs,
                                                 const float* __restrict__ Wm,
                                                 const float* __restrict__ bias,
                                                 const void* __restrict__ pts_raw,
                                                 float* __restrict__ out) {
    __shared__ float hs[8192];   // swizzled h_last (reused as S scratch in last block)
    __shared__ float sblk[128];  // block-local S accumulation [r*8 + b]
    __shared__ int spts[16];     // points, width-detected
    __shared__ int s_last;

    const int tid = threadIdx.x;

    if (tid < 16) {
        // Detect int64 vs int32 points: values < 4096, so int64 data has all-zero hi words.
        const ull* pw = (const ull*)pts_raw;
        ull h = 0;
#pragma unroll
        for (int i = 0; i < 8; i++) h |= (pw[i] >> 32);
        bool is64 = (h == 0ULL);
        spts[tid] = is64 ? (int)((const long long*)pts_raw)[tid]
                         : ((const int*)pts_raw)[tid];
    }
    if (tid < 128) sblk[tid] = 0.f;

    // Stage h_last[b][k] = lhs[b, T-1, k] with XOR swizzle on 16B chunks.
#pragma unroll
    for (int i = 0; i < 32; i++) {
        int idx = tid + i * 256;
        int b = idx >> 10, k = idx & 1023;
        int idx16 = k * 2 + (b >> 2);
        int s = idx16 ^ ((idx16 >> 3) & 7);
        hs[s * 4 + (b & 3)] = lhs[b * (TT * DD) + (TT - 1) * DD + k];
    }
    __syncthreads();

    const int warp = tid >> 5, lane = tid & 31;
    const int rgrp = lane >> 3, c = lane & 7;
    const int rowbase = blockIdx.x * 128 + warp * 16;  // 16 rows per warp
    // Stream q (0..3) handles row rowbase + q*4 + rgrp
    const float4* P = (const float4*)Wm + (size_t)(rowbase + rgrp) * 256 + c;
    const ulonglong2* h8 = (const ulonglong2*)hs;

    // acc[q][p]: packed f32x2, pair p holds batches (2p, 2p+1) for stream q's row
    ull acc[4][4] = {};

    float4 w[4];
#pragma unroll
    for (int q = 0; q < 4; q++) w[q] = __ldcs(&P[q * 1024]);

    for (int j = 0; j < 32; j++) {
        int jn = (j + 1) & 31;  // wrap: last iter reloads j=0 (L1/L2 hit, branchless)
        float4 n[4];
#pragma unroll
        for (int q = 0; q < 4; q++) n[q] = __ldcs(&P[q * 1024 + jn * 8]);

        int k0 = j * 64 + c * 8;  // = (k index)*2 base for the ulonglong2 view
#define STEP(comp, kk)                                                        \
    do {                                                                      \
        int i16 = k0 + 2 * (kk);                                              \
        int sw = (i16 >> 3) & 7;                                              \
        ulonglong2 hA = h8[i16 ^ sw];       /* batches 0-3 */                 \
        ulonglong2 hB = h8[(i16 + 1) ^ sw]; /* batches 4-7 */                 \
        _Pragma("unroll")                                                     \
        for (int q = 0; q < 4; q++) {                                         \
            ull wd = packw(w[q].comp);                                        \
            fma2(acc[q][0], wd, hA.x); fma2(acc[q][1], wd, hA.y);             \
            fma2(acc[q][2], wd, hB.x); fma2(acc[q][3], wd, hB.y);             \
        }                                                                     \
    } while (0)
        STEP(x, 0);
        STEP(y, 1);
        STEP(z, 2);
        STEP(w, 3);
#undef STEP
#pragma unroll
        for (int q = 0; q < 4; q++) w[q] = n[q];
    }

    // Per-stream: unpack, reduce-scatter so lane c ends with batch c's full sum.
    float tot[4];
#pragma unroll
    for (int q = 0; q < 4; q++) {
        float s[8];
#pragma unroll
        for (int p = 0; p < 4; p++) {
            s[2 * p] = lo32(acc[q][p]);
            s[2 * p + 1] = hi32(acc[q][p]);
        }
        tot[q] = rscatter8(s, c);
    }

    // Emit: every lane handles batch b=c for its 4 rows. Conflict-free smem atomics.
#pragma unroll
    for (int q = 0; q < 4; q++) {
        int g = rowbase + q * 4 + rgrp;
        float ev = expf(tot[q] + __ldg(&bias[g]));
        int r = g & (RR - 1);
        atomicAdd(&sblk[r * 8 + c], ev);
        int hidx = g >> 16;
        int v = (g >> 4) & (VV - 1);
        if (v == spts[c * 2 + hidx]) g_E[c * 32 + hidx * 16 + r] = ev;
    }

    __syncthreads();
    if (tid < 128) g_Spart[blockIdx.x][tid] = sblk[tid];
    __threadfence();
    __syncthreads();
    if (tid == 0) {
        unsigned o = atomicAdd(&g_count, 1);
        s_last = (o == (unsigned)(gridDim.x - 1));
    }
    __syncthreads();

    if (s_last) {
        // Final reduction: thread = (h, b, r); blocks [h*512, h*512+512) cover head h.
        int r = tid & 15, b = (tid >> 4) & 7, h = tid >> 7;
        float a = 0.f;
#pragma unroll 8
        for (int i = 0; i < NBLK / 2; i++) a += g_Spart[h * (NBLK / 2) + i][r * 8 + b];
        hs[b * 32 + h * 16 + r] = a;  // reuse hs as S[b][h][r]
        __syncthreads();
        if (tid < 8) {
            float n = 0.f, p = 0.f;
#pragma unroll
            for (int rr = 0; rr < 16; rr++) {
                n += hs[tid * 32 + rr] * hs[tid * 32 + 16 + rr];
                p += g_E[tid * 32 + rr] * g_E[tid * 32 + 16 + rr];
            }
            out[tid] = p;       // p_eval
            out[8 + tid] = n;   // norm_const
        }
        if (tid == 0) g_count = 0;  // reset for next graph replay
    }
}

extern "C" void kernel_launch(void* const* d_in, const int* in_sizes, int n_in,
                              void* d_out, int out_size) {
    // Identify inputs by element count (robust to ordering)
    const float* lhs = nullptr;
    const float* Wm = nullptr;
    const float* bias = nullptr;
    const void* pts = nullptr;
    for (int i = 0; i < n_in; i++) {
        int sz = in_sizes[i];
        if (sz == GG * DD) Wm = (const float*)d_in[i];
        else if (sz == BB * TT * DD) lhs = (const float*)d_in[i];
        else if (sz == GG) bias = (const float*)d_in[i];
        else if (sz == BB * HH) pts = d_in[i];
    }
    if (!lhs) lhs = (const float*)d_in[0];
    if (!Wm) Wm = (const float*)d_in[1];
    if (!bias) bias = (const float*)d_in[2];
    if (!pts) pts = d_in[3];

    k_main<<<NBLK, 256>>>(lhs, Wm, bias, pts, (float*)d_out);
}